// round 8
// baseline (speedup 1.0000x reference)
#include <cuda_runtime.h>
#include <cuda_fp16.h>
#include <cstdint>

#define NMAX_NODES 100000
#define IN_F 256
#define OUT_F 128
#define ELL_CAP 96

// ---------------- scratch (device globals) ----------------
__device__ int      g_cursor[NMAX_NODES];                // in-degree after fill
__device__ int      g_ell[(size_t)NMAX_NODES * ELL_CAP];
// g_msgh[row*256 + 2f] = half2(mean_msg[f], var_msg[f])
__device__ __half   g_msgh[(size_t)NMAX_NODES * 256];
// B in per-thread mma-fragment order: [c8][kl4][wn4][j8][lane32][e2], tf32 bits
__device__ uint32_t g_Bfrag[65536];

// ---------------- small kernels ----------------
__global__ void zero_kernel(int n_nodes) {
    int i = blockIdx.x * blockDim.x + threadIdx.x;
    if (i < n_nodes) g_cursor[i] = 0;
}

__global__ void fill_kernel(const int* __restrict__ src,
                            const int* __restrict__ dst, int E) {
    int i = blockIdx.x * blockDim.x + threadIdx.x;
    if (i >= E) return;
    int d = dst[i];
    int p = atomicAdd(&g_cursor[d], 1);
    if (p < ELL_CAP) g_ell[(size_t)d * ELL_CAP + p] = src[i];
}

// Pack W into mma.sync B-fragment order, interleaved cols c=2f+h (h:0=mean,1=var).
__global__ void bfrag_kernel(const float* __restrict__ Wm,
                             const float* __restrict__ Wv) {
    int tid = blockIdx.x * blockDim.x + threadIdx.x;    // 65536
    int e    = tid & 1;
    int lane = (tid >> 1) & 31;
    int j    = (tid >> 6) & 7;
    int wn   = (tid >> 9) & 3;
    int kl   = (tid >> 11) & 3;
    int c    = tid >> 13;
    int k    = c * 32 + kl * 8 + (lane & 3) + e * 4;
    int ncol = wn * 64 + j * 8 + (lane >> 2);
    int f    = ncol >> 1;
    float val = (ncol & 1) ? Wv[k * OUT_F + f] : Wm[k * OUT_F + f];
    uint32_t t;
    asm("cvt.rna.tf32.f32 %0, %1;" : "=r"(t) : "f"(val));
    g_Bfrag[tid] = t;
}

// ---------------- tf32 mma.sync GEMM + message epilogue ----------------
// CTA: 64 rows x 256 cols, 256 threads = 8 warps (2m x 4n), warp tile 32x64,
// m16n8k8 mma, K chunked by 32. 2 CTAs/SM for latency hiding.
// A: cp.async double-buffered (raw fp32 bits). B: batched LDG (MLP=8).
__global__ void __launch_bounds__(256, 2) gemm_msg_kernel(
    const float* __restrict__ feat, int N)
{
    __shared__ uint32_t As[2][64 * 36];    // padded stride 36, 9216 B per buffer

    const int tid  = threadIdx.x;
    const int warp = tid >> 5;
    const int lane = tid & 31;
    const int wm   = warp >> 2;     // 0..1 : row group of 32
    const int wn   = warp & 3;      // 0..3 : col group of 64 (32 features)
    const int g    = lane >> 2;     // 0..7
    const int tc   = lane & 3;      // 0..3
    const int row0 = blockIdx.x * 64;

    uint32_t sbA;
    asm("{ .reg .u64 t; cvta.to.shared.u64 t, %1; cvt.u32.u64 %0, t; }"
        : "=r"(sbA) : "l"(&As[0][0]));

    float d[2][8][4];
    #pragma unroll
    for (int mt = 0; mt < 2; mt++)
        #pragma unroll
        for (int j = 0; j < 8; j++)
            #pragma unroll
            for (int u = 0; u < 4; u++) d[mt][j][u] = 0.f;

    // stage A-tile chunk c into buffer buf (512 x 16B pieces, 2 per thread)
    auto stage = [&](int c, int buf) {
        uint32_t dstb = sbA + buf * 9216;
        #pragma unroll
        for (int i = 0; i < 2; i++) {
            int idx = tid + 256 * i;       // 0..511
            int r = idx >> 3, q = idx & 7;
            int gr = row0 + r; if (gr >= N) gr = N - 1;
            const float* src = feat + (size_t)gr * IN_F + c * 32 + q * 4;
            uint32_t dst = dstb + (uint32_t)(r * 36 + q * 4) * 4;
            asm volatile("cp.async.cg.shared.global [%0], [%1], 16;"
                         :: "r"(dst), "l"(src) : "memory");
        }
        asm volatile("cp.async.commit_group;" ::: "memory");
    };

    stage(0, 0);

    for (int c = 0; c < 8; c++) {
        const int buf = c & 1;
        if (c + 1 < 8) {
            stage(c + 1, buf ^ 1);
            asm volatile("cp.async.wait_group 1;" ::: "memory");
        } else {
            asm volatile("cp.async.wait_group 0;" ::: "memory");
        }
        __syncthreads();

        const uint32_t* Ab = &As[buf][0];
        #pragma unroll
        for (int kl = 0; kl < 4; kl++) {
            // batched B fragment loads: 8 independent LDG.64 in flight
            const uint2* bbase = (const uint2*)(g_Bfrag + c * 8192 +
                                                ((kl * 4 + wn) * 8) * 64) + lane;
            uint2 breg[8];
            #pragma unroll
            for (int j = 0; j < 8; j++) breg[j] = __ldg(bbase + j * 32);

            // A fragments (conflict-free LDS.32)
            uint32_t a[2][4];
            #pragma unroll
            for (int mt = 0; mt < 2; mt++) {
                int m0 = wm * 32 + mt * 16;
                int kb = kl * 8;
                a[mt][0] = Ab[(m0 + g)     * 36 + kb + tc];
                a[mt][1] = Ab[(m0 + g + 8) * 36 + kb + tc];
                a[mt][2] = Ab[(m0 + g)     * 36 + kb + tc + 4];
                a[mt][3] = Ab[(m0 + g + 8) * 36 + kb + tc + 4];
            }
            #pragma unroll
            for (int j = 0; j < 8; j++) {
                #pragma unroll
                for (int mt = 0; mt < 2; mt++) {
                    asm volatile(
                        "mma.sync.aligned.m16n8k8.row.col.f32.tf32.tf32.f32 "
                        "{%0,%1,%2,%3}, {%4,%5,%6,%7}, {%8,%9}, {%0,%1,%2,%3};"
                        : "+f"(d[mt][j][0]), "+f"(d[mt][j][1]),
                          "+f"(d[mt][j][2]), "+f"(d[mt][j][3])
                        : "r"(a[mt][0]), "r"(a[mt][1]), "r"(a[mt][2]), "r"(a[mt][3]),
                          "r"(breg[j].x), "r"(breg[j].y));
                }
            }
        }
        __syncthreads();
    }

    // ---- epilogue ----
    #pragma unroll
    for (int mt = 0; mt < 2; mt++) {
        int r0 = row0 + wm * 32 + mt * 16 + g;
        int r1 = r0 + 8;
        bool va = r0 < N, vb = r1 < N;
        float n1a = 0.f, n2a = 0.f, n1b = 0.f, n2b = 0.f;
        if (va) {
            int dg = g_cursor[r0];
            float df = (float)(dg > 0 ? dg : 1);
            n1a = rsqrtf(df); n2a = n1a * n1a;
        }
        if (vb) {
            int dg = g_cursor[r1];
            float df = (float)(dg > 0 ? dg : 1);
            n1b = rsqrtf(df); n2b = n1b * n1b;
        }
        #pragma unroll
        for (int j = 0; j < 8; j++) {
            int f = wn * 32 + j * 4 + tc;
            if (va) {
                float m = fmaxf(d[mt][j][0], 0.f);
                float v = fmaxf(d[mt][j][1], 0.f);
                float att = __expf(-v);
                __half2 h = __floats2half2_rn(m * att * n1a, v * att * att * n2a);
                *(__half2*)(g_msgh + (size_t)r0 * 256 + 2 * f) = h;
            }
            if (vb) {
                float m = fmaxf(d[mt][j][2], 0.f);
                float v = fmaxf(d[mt][j][3], 0.f);
                float att = __expf(-v);
                __half2 h = __floats2half2_rn(m * att * n1b, v * att * att * n2b);
                *(__half2*)(g_msgh + (size_t)r1 * 256 + 2 * f) = h;
            }
        }
    }
}

// ---------------- gather: one warp per dst node, MLP-8 batched loads ----------------
__global__ void __launch_bounds__(256) gather_kernel(
    float* __restrict__ out_mean,
    float* __restrict__ out_var,
    int N)
{
    int warp = (blockIdx.x * blockDim.x + threadIdx.x) >> 5;
    int lane = threadIdx.x & 31;
    if (warp >= N) return;
    const int node = warp;

    int deg = g_cursor[node];
    int cnt_total = deg < ELL_CAP ? deg : ELL_CAP;

    float am0 = 0.f, am1 = 0.f, am2 = 0.f, am3 = 0.f;
    float av0 = 0.f, av1 = 0.f, av2 = 0.f, av3 = 0.f;

    const int* ell_row = g_ell + (size_t)node * ELL_CAP;

    for (int base = 0; base < cnt_total; base += 32) {
        int cnt = cnt_total - base; if (cnt > 32) cnt = 32;
        int s_l = (lane < cnt) ? ell_row[base + lane] : 0;
        for (int e0 = 0; e0 < cnt; e0 += 8) {
            int m = cnt - e0; if (m > 8) m = 8;
            uint4 q[8];
            #pragma unroll
            for (int i = 0; i < 8; i++) {
                if (i < m) {
                    int s = __shfl_sync(0xffffffffu, s_l, e0 + i);
                    q[i] = *(const uint4*)(g_msgh + (size_t)s * 256 + lane * 8);
                }
            }
            #pragma unroll
            for (int i = 0; i < 8; i++) {
                if (i < m) {
                    float2 f0 = __half22float2(*(__half2*)&q[i].x);
                    float2 f1 = __half22float2(*(__half2*)&q[i].y);
                    float2 f2 = __half22float2(*(__half2*)&q[i].z);
                    float2 f3 = __half22float2(*(__half2*)&q[i].w);
                    am0 += f0.x; av0 += f0.y;
                    am1 += f1.x; av1 += f1.y;
                    am2 += f2.x; av2 += f2.y;
                    am3 += f3.x; av3 += f3.y;
                }
            }
        }
    }

    float degf = (float)(deg > 0 ? deg : 1);
    float n1 = rsqrtf(degf);
    float n2 = n1 * n1;

    float4 om = make_float4(am0 * n1, am1 * n1, am2 * n1, am3 * n1);
    float4 ov = make_float4(av0 * n2, av1 * n2, av2 * n2, av3 * n2);
    *(float4*)(out_mean + (size_t)node * 128 + lane * 4) = om;
    *(float4*)(out_var  + (size_t)node * 128 + lane * 4) = ov;
}

// ---------------- launch ----------------
extern "C" void kernel_launch(void* const* d_in, const int* in_sizes, int n_in,
                              void* d_out, int out_size) {
    const float* feat = (const float*)d_in[0];
    const float* Wm   = (const float*)d_in[1];
    const float* Wv   = (const float*)d_in[2];
    const int*   src  = (const int*)d_in[3];
    const int*   dst  = (const int*)d_in[4];

    int N = in_sizes[0] / IN_F;           // 100000
    int E = in_sizes[3];                  // 1600000

    float* out      = (float*)d_out;
    float* out_mean = out;
    float* out_var  = out + (size_t)N * OUT_F;

    zero_kernel<<<(N + 255) / 256, 256>>>(N);
    fill_kernel<<<(E + 255) / 256, 256>>>(src, dst, E);
    bfrag_kernel<<<256, 256>>>(Wm, Wv);

    gemm_msg_kernel<<<(N + 63) / 64, 256>>>(feat, N);

    int gblocks = (N * 32 + 255) / 256;
    gather_kernel<<<gblocks, 256>>>(out_mean, out_var, N);
}

// round 9
// speedup vs baseline: 1.3633x; 1.3633x over previous
#include <cuda_runtime.h>
#include <cuda_fp16.h>
#include <cstdint>

#define NMAX_NODES 100000
#define IN_F 256
#define OUT_F 128
#define ELL_CAP 96

// ---------------- scratch (device globals) ----------------
__device__ int      g_cursor[NMAX_NODES];                // in-degree after fill
__device__ int      g_ell[(size_t)NMAX_NODES * ELL_CAP];
// g_msgh[row*256 + 2f] = half2(mean_msg[f], var_msg[f])
__device__ __half   g_msgh[(size_t)NMAX_NODES * 256];
// B fragment image: [c8][kl4][wq8][j4][lane32][e2], tf32 bits
__device__ uint32_t g_Bfrag[65536];

// ---------------- small kernels ----------------
__global__ void zero_kernel(int n_nodes) {
    int i = blockIdx.x * blockDim.x + threadIdx.x;
    if (i < n_nodes) g_cursor[i] = 0;
}

__global__ void fill_kernel(const int* __restrict__ src,
                            const int* __restrict__ dst, int E) {
    int i = blockIdx.x * blockDim.x + threadIdx.x;
    if (i >= E) return;
    int d = dst[i];
    int p = atomicAdd(&g_cursor[d], 1);
    if (p < ELL_CAP) g_ell[(size_t)d * ELL_CAP + p] = src[i];
}

// Pack W into per-warp fragment order; interleaved cols c=2f+h (0=mean,1=var).
__global__ void bfrag_kernel(const float* __restrict__ Wm,
                             const float* __restrict__ Wv) {
    int tid = blockIdx.x * blockDim.x + threadIdx.x;    // 65536
    int e    = tid & 1;
    int lane = (tid >> 1) & 31;
    int j    = (tid >> 6) & 3;
    int wq   = (tid >> 8) & 7;
    int kl   = (tid >> 11) & 3;
    int c    = tid >> 13;
    int k    = c * 32 + kl * 8 + (lane & 3) + e * 4;
    int ncol = wq * 32 + j * 8 + (lane >> 2);
    int f    = ncol >> 1;
    float val = (ncol & 1) ? Wv[k * OUT_F + f] : Wm[k * OUT_F + f];
    uint32_t t;
    asm("cvt.rna.tf32.f32 %0, %1;" : "=r"(t) : "f"(val));
    g_Bfrag[tid] = t;
}

// ---------------- tf32 mma.sync GEMM + message epilogue ----------------
// CTA: 64 rows x 256 cols, 256 threads = 8 warps, warp tile 64x32
// (mt=0..3 row groups of 16, j=0..3 n8-tiles). No B duplication across warps.
// A: cp.async double-buffered (raw fp32 bits). B: batched LDG (4 in flight).
__global__ void __launch_bounds__(256, 2) gemm_msg_kernel(
    const float* __restrict__ feat, int N)
{
    __shared__ uint32_t As[2][64 * 36];    // padded stride 36, 9216 B per buffer

    const int tid  = threadIdx.x;
    const int warp = tid >> 5;      // 0..7 : col group of 32 (16 features)
    const int lane = tid & 31;
    const int g    = lane >> 2;     // 0..7
    const int tc   = lane & 3;      // 0..3
    const int row0 = blockIdx.x * 64;

    uint32_t sbA;
    asm("{ .reg .u64 t; cvta.to.shared.u64 t, %1; cvt.u32.u64 %0, t; }"
        : "=r"(sbA) : "l"(&As[0][0]));

    float d[4][4][4];   // [mt][j][frag]
    #pragma unroll
    for (int mt = 0; mt < 4; mt++)
        #pragma unroll
        for (int j = 0; j < 4; j++)
            #pragma unroll
            for (int u = 0; u < 4; u++) d[mt][j][u] = 0.f;

    // stage A-tile chunk c into buffer buf (512 x 16B pieces, 2 per thread)
    auto stage = [&](int c, int buf) {
        uint32_t dstb = sbA + buf * 9216;
        #pragma unroll
        for (int i = 0; i < 2; i++) {
            int idx = tid + 256 * i;       // 0..511
            int r = idx >> 3, q = idx & 7;
            int gr = row0 + r; if (gr >= N) gr = N - 1;
            const float* src = feat + (size_t)gr * IN_F + c * 32 + q * 4;
            uint32_t dst = dstb + (uint32_t)(r * 36 + q * 4) * 4;
            asm volatile("cp.async.cg.shared.global [%0], [%1], 16;"
                         :: "r"(dst), "l"(src) : "memory");
        }
        asm volatile("cp.async.commit_group;" ::: "memory");
    };

    stage(0, 0);

    for (int c = 0; c < 8; c++) {
        const int buf = c & 1;
        if (c + 1 < 8) {
            stage(c + 1, buf ^ 1);
            asm volatile("cp.async.wait_group 1;" ::: "memory");
        } else {
            asm volatile("cp.async.wait_group 0;" ::: "memory");
        }
        __syncthreads();

        const uint32_t* Ab = &As[buf][0];
        #pragma unroll
        for (int kl = 0; kl < 4; kl++) {
            // B fragments: 4 independent LDG.64 in flight (no cross-warp dup)
            const uint2* bbase = (const uint2*)(g_Bfrag + c * 8192 + kl * 2048 +
                                                warp * 256) + lane;
            uint2 breg[4];
            #pragma unroll
            for (int j = 0; j < 4; j++) breg[j] = __ldg(bbase + j * 32);

            // A fragments for all 4 row groups (conflict-free LDS.32)
            uint32_t a[4][4];
            #pragma unroll
            for (int mt = 0; mt < 4; mt++) {
                int m0 = mt * 16;
                int kb = kl * 8;
                a[mt][0] = Ab[(m0 + g)     * 36 + kb + tc];
                a[mt][1] = Ab[(m0 + g + 8) * 36 + kb + tc];
                a[mt][2] = Ab[(m0 + g)     * 36 + kb + tc + 4];
                a[mt][3] = Ab[(m0 + g + 8) * 36 + kb + tc + 4];
            }
            #pragma unroll
            for (int j = 0; j < 4; j++) {
                #pragma unroll
                for (int mt = 0; mt < 4; mt++) {
                    asm volatile(
                        "mma.sync.aligned.m16n8k8.row.col.f32.tf32.tf32.f32 "
                        "{%0,%1,%2,%3}, {%4,%5,%6,%7}, {%8,%9}, {%0,%1,%2,%3};"
                        : "+f"(d[mt][j][0]), "+f"(d[mt][j][1]),
                          "+f"(d[mt][j][2]), "+f"(d[mt][j][3])
                        : "r"(a[mt][0]), "r"(a[mt][1]), "r"(a[mt][2]), "r"(a[mt][3]),
                          "r"(breg[j].x), "r"(breg[j].y));
                }
            }
        }
        __syncthreads();
    }

    // ---- epilogue: (d0,d1)=(mean,var) row r0; (d2,d3) row r0+8 ----
    #pragma unroll
    for (int mt = 0; mt < 4; mt++) {
        int r0 = row0 + mt * 16 + g;
        int r1 = r0 + 8;
        bool va = r0 < N, vb = r1 < N;
        float n1a = 0.f, n2a = 0.f, n1b = 0.f, n2b = 0.f;
        if (va) {
            int dg = g_cursor[r0];
            float df = (float)(dg > 0 ? dg : 1);
            n1a = rsqrtf(df); n2a = n1a * n1a;
        }
        if (vb) {
            int dg = g_cursor[r1];
            float df = (float)(dg > 0 ? dg : 1);
            n1b = rsqrtf(df); n2b = n1b * n1b;
        }
        #pragma unroll
        for (int j = 0; j < 4; j++) {
            int f = warp * 16 + j * 4 + tc;
            if (va) {
                float m = fmaxf(d[mt][j][0], 0.f);
                float v = fmaxf(d[mt][j][1], 0.f);
                float att = __expf(-v);
                __half2 h = __floats2half2_rn(m * att * n1a, v * att * att * n2a);
                *(__half2*)(g_msgh + (size_t)r0 * 256 + 2 * f) = h;
            }
            if (vb) {
                float m = fmaxf(d[mt][j][2], 0.f);
                float v = fmaxf(d[mt][j][3], 0.f);
                float att = __expf(-v);
                __half2 h = __floats2half2_rn(m * att * n1b, v * att * att * n2b);
                *(__half2*)(g_msgh + (size_t)r1 * 256 + 2 * f) = h;
            }
        }
    }
}

// ---------------- gather: one warp per dst node (R7 form) ----------------
__global__ void __launch_bounds__(256) gather_kernel(
    float* __restrict__ out_mean,
    float* __restrict__ out_var,
    int N)
{
    int warp = (blockIdx.x * blockDim.x + threadIdx.x) >> 5;
    int lane = threadIdx.x & 31;
    if (warp >= N) return;
    const int node = warp;

    int deg = g_cursor[node];
    int cnt_total = deg < ELL_CAP ? deg : ELL_CAP;

    float am0 = 0.f, am1 = 0.f, am2 = 0.f, am3 = 0.f;
    float av0 = 0.f, av1 = 0.f, av2 = 0.f, av3 = 0.f;

    const int* ell_row = g_ell + (size_t)node * ELL_CAP;

    for (int base = 0; base < cnt_total; base += 32) {
        int cnt = cnt_total - base; if (cnt > 32) cnt = 32;
        int s_l = (lane < cnt) ? ell_row[base + lane] : 0;
        #pragma unroll 4
        for (int e = 0; e < cnt; e++) {
            int s = __shfl_sync(0xffffffffu, s_l, e);
            uint4 q = *(const uint4*)(g_msgh + (size_t)s * 256 + lane * 8);
            float2 f0 = __half22float2(*(__half2*)&q.x);
            float2 f1 = __half22float2(*(__half2*)&q.y);
            float2 f2 = __half22float2(*(__half2*)&q.z);
            float2 f3 = __half22float2(*(__half2*)&q.w);
            am0 += f0.x; av0 += f0.y;
            am1 += f1.x; av1 += f1.y;
            am2 += f2.x; av2 += f2.y;
            am3 += f3.x; av3 += f3.y;
        }
    }

    float degf = (float)(deg > 0 ? deg : 1);
    float n1 = rsqrtf(degf);
    float n2 = n1 * n1;

    float4 om = make_float4(am0 * n1, am1 * n1, am2 * n1, am3 * n1);
    float4 ov = make_float4(av0 * n2, av1 * n2, av2 * n2, av3 * n2);
    *(float4*)(out_mean + (size_t)node * 128 + lane * 4) = om;
    *(float4*)(out_var  + (size_t)node * 128 + lane * 4) = ov;
}

// ---------------- launch ----------------
extern "C" void kernel_launch(void* const* d_in, const int* in_sizes, int n_in,
                              void* d_out, int out_size) {
    const float* feat = (const float*)d_in[0];
    const float* Wm   = (const float*)d_in[1];
    const float* Wv   = (const float*)d_in[2];
    const int*   src  = (const int*)d_in[3];
    const int*   dst  = (const int*)d_in[4];

    int N = in_sizes[0] / IN_F;           // 100000
    int E = in_sizes[3];                  // 1600000

    float* out      = (float*)d_out;
    float* out_mean = out;
    float* out_var  = out + (size_t)N * OUT_F;

    zero_kernel<<<(N + 255) / 256, 256>>>(N);
    fill_kernel<<<(E + 255) / 256, 256>>>(src, dst, E);
    bfrag_kernel<<<256, 256>>>(Wm, Wv);

    gemm_msg_kernel<<<(N + 63) / 64, 256>>>(feat, N);

    int gblocks = (N * 32 + 255) / 256;
    gather_kernel<<<gblocks, 256>>>(out_mean, out_var, N);
}

// round 10
// speedup vs baseline: 1.6066x; 1.1785x over previous
#include <cuda_runtime.h>
#include <cuda_fp16.h>
#include <cstdint>

#define NMAX_NODES 100000
#define IN_F 256
#define OUT_F 128
#define ELL_CAP 96

// ---------------- scratch (device globals) ----------------
__device__ int      g_cursor[NMAX_NODES];                // in-degree after fill
__device__ int      g_ell[(size_t)NMAX_NODES * ELL_CAP];
// g_msgh[row*256 + 2f] = half2(mean_msg[f], var_msg[f])
__device__ __half   g_msgh[(size_t)NMAX_NODES * 256];
// fp16 B fragment image: [ck16][wq8][j4][lane32][e2] half2s (128KB)
__device__ uint32_t g_Bfragh[32768];

// ---------------- small kernels ----------------
__global__ void zero_kernel(int n_nodes) {
    int i = blockIdx.x * blockDim.x + threadIdx.x;
    if (i < n_nodes) g_cursor[i] = 0;
}

__global__ void fill_kernel(const int* __restrict__ src,
                            const int* __restrict__ dst, int E) {
    int i = blockIdx.x * blockDim.x + threadIdx.x;
    if (i >= E) return;
    int d = dst[i];
    int p = atomicAdd(&g_cursor[d], 1);
    if (p < ELL_CAP) g_ell[(size_t)d * ELL_CAP + p] = src[i];
}

// Pack W into fp16 m16n8k16 B-fragment order; interleaved cols c=2f+h.
// Fragment reg e holds halfs (k_local = tc*2+e*8, +1) for n = wq*32+j*8+g.
__global__ void bfrag_kernel(const float* __restrict__ Wm,
                             const float* __restrict__ Wv) {
    int tid = blockIdx.x * blockDim.x + threadIdx.x;    // 32768
    int e    = tid & 1;
    int lane = (tid >> 1) & 31;
    int j    = (tid >> 6) & 3;
    int wq   = (tid >> 8) & 7;
    int ck   = tid >> 11;          // 0..15 : c*2 + kl2
    int tc = lane & 3, g = lane >> 2;
    int k = ck * 16 + tc * 2 + e * 8;
    int ncol = wq * 32 + j * 8 + g;
    int f = ncol >> 1;
    const float* W = (ncol & 1) ? Wv : Wm;
    float lo = W[k * OUT_F + f];
    float hi = W[(k + 1) * OUT_F + f];
    __half2 h = __floats2half2_rn(lo, hi);
    g_Bfragh[tid] = *(uint32_t*)&h;
}

// ---------------- fp16 mma.sync GEMM + message epilogue ----------------
// CTA: 64 rows x 256 cols (c=2f+h), 256 threads = 8 warps, warp tile 64x32,
// m16n8k16, K chunked by 32 (2 k16 steps). 2 CTAs/SM.
// A: fp32 LDG prefetch -> cvt -> fp16 STS (144B row stride, conflict-free frags).
__global__ void __launch_bounds__(256, 2) gemm_msg_kernel(
    const float* __restrict__ feat, int N)
{
    __shared__ __align__(16) __half As[2][64 * 72];  // 144B stride, 9216B/buf

    const int tid  = threadIdx.x;
    const int warp = tid >> 5;      // 0..7 : col group of 32 (16 features)
    const int lane = tid & 31;
    const int g    = lane >> 2;     // 0..7
    const int tc   = lane & 3;      // 0..3
    const int row0 = blockIdx.x * 64;

    float d[4][4][4];   // [mt][j][frag]
    #pragma unroll
    for (int mt = 0; mt < 4; mt++)
        #pragma unroll
        for (int j = 0; j < 4; j++)
            #pragma unroll
            for (int u = 0; u < 4; u++) d[mt][j][u] = 0.f;

    const int ar = tid >> 2;       // 0..63 row
    const int aq = tid & 3;        // 0..3 : 8-float piece
    float4 pre0, pre1;

    auto ldA = [&](int c) {
        int gr = row0 + ar; if (gr >= N) gr = N - 1;
        const float4* p = (const float4*)(feat + (size_t)gr * IN_F + c * 32 + aq * 8);
        pre0 = p[0]; pre1 = p[1];
    };
    auto stA = [&](int buf) {
        __half2 h0 = __floats2half2_rn(pre0.x, pre0.y);
        __half2 h1 = __floats2half2_rn(pre0.z, pre0.w);
        __half2 h2 = __floats2half2_rn(pre1.x, pre1.y);
        __half2 h3 = __floats2half2_rn(pre1.z, pre1.w);
        uint4 pk;
        pk.x = *(unsigned*)&h0; pk.y = *(unsigned*)&h1;
        pk.z = *(unsigned*)&h2; pk.w = *(unsigned*)&h3;
        *(uint4*)&As[buf][ar * 72 + aq * 8] = pk;
    };

    ldA(0);

    for (int c = 0; c < 8; c++) {
        const int buf = c & 1;
        stA(buf);
        __syncthreads();
        if (c + 1 < 8) ldA(c + 1);   // LDG in flight across compute

        const __half* Ab = &As[buf][0];
        #pragma unroll
        for (int kl2 = 0; kl2 < 2; kl2++) {
            const int ck = c * 2 + kl2;
            // B fragments: 4 independent LDG.64
            const uint2* bb = (const uint2*)(g_Bfragh + ((ck * 8 + warp) * 4) * 64) + lane;
            uint2 breg[4];
            #pragma unroll
            for (int j = 0; j < 4; j++) breg[j] = __ldg(bb + j * 32);

            // A fragments for 4 row groups (conflict-free LDS.32)
            uint32_t a[4][4];
            #pragma unroll
            for (int mt = 0; mt < 4; mt++) {
                const __half* ap0 = Ab + (mt * 16 + g) * 72 + kl2 * 16 + tc * 2;
                const __half* ap1 = ap0 + 8 * 72;
                a[mt][0] = *(const uint32_t*)(ap0);
                a[mt][1] = *(const uint32_t*)(ap1);
                a[mt][2] = *(const uint32_t*)(ap0 + 8);
                a[mt][3] = *(const uint32_t*)(ap1 + 8);
            }
            #pragma unroll
            for (int j = 0; j < 4; j++) {
                #pragma unroll
                for (int mt = 0; mt < 4; mt++) {
                    asm volatile(
                        "mma.sync.aligned.m16n8k16.row.col.f32.f16.f16.f32 "
                        "{%0,%1,%2,%3}, {%4,%5,%6,%7}, {%8,%9}, {%0,%1,%2,%3};"
                        : "+f"(d[mt][j][0]), "+f"(d[mt][j][1]),
                          "+f"(d[mt][j][2]), "+f"(d[mt][j][3])
                        : "r"(a[mt][0]), "r"(a[mt][1]), "r"(a[mt][2]), "r"(a[mt][3]),
                          "r"(breg[j].x), "r"(breg[j].y));
                }
            }
        }
        __syncthreads();   // protect buf before stA(c+1) overwrites other buffer path
    }

    // ---- epilogue: (d0,d1)=(mean,var) row r0; (d2,d3) row r0+8 ----
    #pragma unroll
    for (int mt = 0; mt < 4; mt++) {
        int r0 = row0 + mt * 16 + g;
        int r1 = r0 + 8;
        bool va = r0 < N, vb = r1 < N;
        float n1a = 0.f, n2a = 0.f, n1b = 0.f, n2b = 0.f;
        if (va) {
            int dg = g_cursor[r0];
            float df = (float)(dg > 0 ? dg : 1);
            n1a = rsqrtf(df); n2a = n1a * n1a;
        }
        if (vb) {
            int dg = g_cursor[r1];
            float df = (float)(dg > 0 ? dg : 1);
            n1b = rsqrtf(df); n2b = n1b * n1b;
        }
        #pragma unroll
        for (int j = 0; j < 4; j++) {
            int f = warp * 16 + j * 4 + tc;
            if (va) {
                float m = fmaxf(d[mt][j][0], 0.f);
                float v = fmaxf(d[mt][j][1], 0.f);
                float att = __expf(-v);
                __half2 h = __floats2half2_rn(m * att * n1a, v * att * att * n2a);
                *(__half2*)(g_msgh + (size_t)r0 * 256 + 2 * f) = h;
            }
            if (vb) {
                float m = fmaxf(d[mt][j][2], 0.f);
                float v = fmaxf(d[mt][j][3], 0.f);
                float att = __expf(-v);
                __half2 h = __floats2half2_rn(m * att * n1b, v * att * att * n2b);
                *(__half2*)(g_msgh + (size_t)r1 * 256 + 2 * f) = h;
            }
        }
    }
}

// ---------------- gather: one warp per dst node (R7 form, known-good) ------
__global__ void __launch_bounds__(256) gather_kernel(
    float* __restrict__ out_mean,
    float* __restrict__ out_var,
    int N)
{
    int warp = (blockIdx.x * blockDim.x + threadIdx.x) >> 5;
    int lane = threadIdx.x & 31;
    if (warp >= N) return;
    const int node = warp;

    int deg = g_cursor[node];
    int cnt_total = deg < ELL_CAP ? deg : ELL_CAP;

    float am0 = 0.f, am1 = 0.f, am2 = 0.f, am3 = 0.f;
    float av0 = 0.f, av1 = 0.f, av2 = 0.f, av3 = 0.f;

    const int* ell_row = g_ell + (size_t)node * ELL_CAP;

    for (int base = 0; base < cnt_total; base += 32) {
        int cnt = cnt_total - base; if (cnt > 32) cnt = 32;
        int s_l = (lane < cnt) ? ell_row[base + lane] : 0;
        #pragma unroll 4
        for (int e = 0; e < cnt; e++) {
            int s = __shfl_sync(0xffffffffu, s_l, e);
            uint4 q = *(const uint4*)(g_msgh + (size_t)s * 256 + lane * 8);
            float2 f0 = __half22float2(*(__half2*)&q.x);
            float2 f1 = __half22float2(*(__half2*)&q.y);
            float2 f2 = __half22float2(*(__half2*)&q.z);
            float2 f3 = __half22float2(*(__half2*)&q.w);
            am0 += f0.x; av0 += f0.y;
            am1 += f1.x; av1 += f1.y;
            am2 += f2.x; av2 += f2.y;
            am3 += f3.x; av3 += f3.y;
        }
    }

    float degf = (float)(deg > 0 ? deg : 1);
    float n1 = rsqrtf(degf);
    float n2 = n1 * n1;

    float4 om = make_float4(am0 * n1, am1 * n1, am2 * n1, am3 * n1);
    float4 ov = make_float4(av0 * n2, av1 * n2, av2 * n2, av3 * n2);
    *(float4*)(out_mean + (size_t)node * 128 + lane * 4) = om;
    *(float4*)(out_var  + (size_t)node * 128 + lane * 4) = ov;
}

// ---------------- launch ----------------
extern "C" void kernel_launch(void* const* d_in, const int* in_sizes, int n_in,
                              void* d_out, int out_size) {
    const float* feat = (const float*)d_in[0];
    const float* Wm   = (const float*)d_in[1];
    const float* Wv   = (const float*)d_in[2];
    const int*   src  = (const int*)d_in[3];
    const int*   dst  = (const int*)d_in[4];

    int N = in_sizes[0] / IN_F;           // 100000
    int E = in_sizes[3];                  // 1600000

    float* out      = (float*)d_out;
    float* out_mean = out;
    float* out_var  = out + (size_t)N * OUT_F;

    zero_kernel<<<(N + 255) / 256, 256>>>(N);
    fill_kernel<<<(E + 255) / 256, 256>>>(src, dst, E);
    bfrag_kernel<<<128, 256>>>(Wm, Wv);

    gemm_msg_kernel<<<(N + 63) / 64, 256>>>(feat, N);

    int gblocks = (N * 32 + 255) / 256;
    gather_kernel<<<gblocks, 256>>>(out_mean, out_var, N);
}